// round 10
// baseline (speedup 1.0000x reference)
#include <cuda_runtime.h>
#include <math.h>

// DamagedPointRepair (8192x8192 fp32):
//   mean  = 3x3 zero-padded box mean * coeff (== in-bounds 3x3 average)
//   mask  = img > 5*mean || img > 1000
//   out   = mask ? floor(4-neighbor avg) : img
//
// R5: L1-wavefront reduction. Halos via warp shuffle (kills stride-16B scalar
// halo loads, which cost 4 L1 wavefronts each) + 4 output rows per thread
// (6 loaded rows per 4 output rows: redundancy 2.0x -> 1.5x).
// Border warps take the scalar generic path (warp-uniform branch).

#define THRE_TIMES 5.0f
#define THRE_POINT 1000.0f
#define FULL_MASK 0xffffffffu

__device__ __forceinline__ void load6g(const float* __restrict__ row, int x0, int W,
                                       bool valid, float v[6]) {
    if (valid) {
        const float4 c = *reinterpret_cast<const float4*>(row + x0);
        v[1] = c.x; v[2] = c.y; v[3] = c.z; v[4] = c.w;
        v[0] = (x0 > 0)     ? __ldg(row + x0 - 1) : 0.0f;
        v[5] = (x0 + 4 < W) ? __ldg(row + x0 + 4) : 0.0f;
    } else {
        v[0] = v[1] = v[2] = v[3] = v[4] = v[5] = 0.0f;
    }
}

// Generic (border-capable) single output row of 4 pixels.
__device__ __forceinline__ void row_generic(const float* __restrict__ img,
                                            float* __restrict__ out,
                                            int y, int x0, int H, int W) {
    const bool has_up = (y > 0);
    const bool has_dn = (y < H - 1);

    float a[6], b[6], c[6];
    load6g(img + (size_t)(y - 1) * W, x0, W, has_up, a);
    load6g(img + (size_t)y * W,       x0, W, true,   b);
    load6g(img + (size_t)(y + 1) * W, x0, W, has_dn, c);

    const float rows_valid = 1.0f + (has_up ? 1.0f : 0.0f) + (has_dn ? 1.0f : 0.0f);

    float4 res;
    float* rp = reinterpret_cast<float*>(&res);
    #pragma unroll
    for (int i = 0; i < 4; i++) {
        const int x = x0 + i;
        const bool has_l = (x > 0);
        const bool has_r = (x < W - 1);

        const float sum9 = (a[i] + a[i + 1] + a[i + 2])
                         + (b[i] + b[i + 1] + b[i + 2])
                         + (c[i] + c[i + 1] + c[i + 2]);

        const float cols_valid = 1.0f + (has_l ? 1.0f : 0.0f) + (has_r ? 1.0f : 0.0f);
        const float count = rows_valid * cols_valid;
        const float coeff = 9.0f / count;
        const float mean  = (sum9 * (1.0f / 9.0f)) * coeff;

        const float v = b[i + 1];
        const bool mask = (v > THRE_TIMES * mean) || (v > THRE_POINT);

        const float nsum = b[i] + b[i + 2] + a[i + 1] + c[i + 1];
        const float cnt  = (has_up ? 1.0f : 0.0f) + (has_dn ? 1.0f : 0.0f)
                         + (has_l  ? 1.0f : 0.0f) + (has_r  ? 1.0f : 0.0f);
        const float repaired = floorf(nsum / cnt);

        rp[i] = mask ? repaired : v;
    }
    *reinterpret_cast<float4*>(out + (size_t)y * W + x0) = res;
}

__global__ void __launch_bounds__(256)
repair_kernel(const float* __restrict__ img, float* __restrict__ out,
              int H, int W) {
    const int lane = threadIdx.x;                       // blockDim.x == 32
    const int x0 = (blockIdx.x * 32 + lane) * 4;        // 4 px wide
    const int y0 = (blockIdx.y * blockDim.y + threadIdx.y) * 4;  // 4 px tall

    const bool valid = (x0 < W) && (y0 < H);
    // Interior: rows y0-1..y0+4 in-bounds, and x halos resolvable
    // (lane 0 edge load needs x0-1 >= 0; lane 31 edge load needs x0+4 <= W-1).
    const bool interior = valid && (x0 >= 4) && (x0 + 8 <= W)
                        && (y0 >= 1) && (y0 + 4 <= H - 1);

    if (__all_sync(FULL_MASK, interior)) {
        const float* base = img + (size_t)(y0 - 1) * W + x0;

        // 6 input rows, one float4 each (MLP batch), halos via shuffle.
        float4 c[6];
        #pragma unroll
        for (int r = 0; r < 6; r++)
            c[r] = *reinterpret_cast<const float4*>(base + (size_t)r * W);

        float L[6][6];
        #pragma unroll
        for (int r = 0; r < 6; r++) {
            float v0 = __shfl_up_sync(FULL_MASK, c[r].w, 1);
            float v5 = __shfl_down_sync(FULL_MASK, c[r].x, 1);
            if (lane == 0)  v0 = __ldg(base + (size_t)r * W - 1);
            if (lane == 31) v5 = __ldg(base + (size_t)r * W + 4);
            L[r][0] = v0;     L[r][1] = c[r].x; L[r][2] = c[r].y;
            L[r][3] = c[r].z; L[r][4] = c[r].w; L[r][5] = v5;
        }

        float* o = out + (size_t)y0 * W + x0;

        #pragma unroll
        for (int pr = 0; pr < 2; pr++) {
            const int k = 2 * pr;  // output rows y0+k, y0+k+1 use L[k..k+3]
            float t[6], WA[6], WB[6];
            #pragma unroll
            for (int j = 0; j < 6; j++) {
                t[j]  = L[k + 1][j] + L[k + 2][j];  // shared middle pair
                WA[j] = L[k][j] + t[j];
                WB[j] = t[j] + L[k + 3][j];
            }

            float4 ra, rb;
            float* pa = reinterpret_cast<float*>(&ra);
            float* pb = reinterpret_cast<float*>(&rb);

            #pragma unroll
            for (int i = 0; i < 4; i++) {
                {   // row y0+k
                    const float v    = L[k + 1][i + 1];
                    const float mean = (WA[i] + WA[i + 1] + WA[i + 2]) * (1.0f / 9.0f);
                    const bool  m    = (v > THRE_TIMES * mean) || (v > THRE_POINT);
                    const float ns   = L[k][i + 1] + L[k + 2][i + 1]
                                     + L[k + 1][i] + L[k + 1][i + 2];
                    pa[i] = m ? floorf(ns * 0.25f) : v;
                }
                {   // row y0+k+1
                    const float v    = L[k + 2][i + 1];
                    const float mean = (WB[i] + WB[i + 1] + WB[i + 2]) * (1.0f / 9.0f);
                    const bool  m    = (v > THRE_TIMES * mean) || (v > THRE_POINT);
                    const float ns   = L[k + 1][i + 1] + L[k + 3][i + 1]
                                     + L[k + 2][i] + L[k + 2][i + 2];
                    pb[i] = m ? floorf(ns * 0.25f) : v;
                }
            }

            *reinterpret_cast<float4*>(o + (size_t)k * W)       = ra;
            *reinterpret_cast<float4*>(o + (size_t)(k + 1) * W) = rb;
        }
    } else {
        if (!valid) return;
        #pragma unroll
        for (int r = 0; r < 4; r++)
            if (y0 + r < H) row_generic(img, out, y0 + r, x0, H, W);
    }
}

extern "C" void kernel_launch(void* const* d_in, const int* in_sizes, int n_in,
                              void* d_out, int out_size) {
    const float* img = (const float*)d_in[0];
    float* out = (float*)d_out;

    long long n = in_sizes[0];
    int side = (int)(sqrt((double)n) + 0.5);
    const int H = side, W = side;

    dim3 block(32, 8);                      // 256 threads; thread tile 4x4
    dim3 grid((W + 127) / 128,              // 32 lanes * 4 px
              (H + 31) / 32);               // 8 thread-rows * 4 px
    repair_kernel<<<grid, block>>>(img, out, H, W);
}

// round 11
// speedup vs baseline: 1.0142x; 1.0142x over previous
#include <cuda_runtime.h>
#include <math.h>

// DamagedPointRepair (8192x8192 fp32):
//   mean  = 3x3 zero-padded box mean * coeff (== in-bounds 3x3 average)
//   mask  = img > 5*mean || img > 1000
//   out   = mask ? floor(4-neighbor avg) : img
//
// R5: L1-wavefront reduction. Halos via warp shuffle (kills stride-16B scalar
// halo loads, which cost 4 L1 wavefronts each) + 4 output rows per thread
// (6 loaded rows per 4 output rows: redundancy 2.0x -> 1.5x).
// Border warps take the scalar generic path (warp-uniform branch).

#define THRE_TIMES 5.0f
#define THRE_POINT 1000.0f
#define FULL_MASK 0xffffffffu

__device__ __forceinline__ void load6g(const float* __restrict__ row, int x0, int W,
                                       bool valid, float v[6]) {
    if (valid) {
        const float4 c = *reinterpret_cast<const float4*>(row + x0);
        v[1] = c.x; v[2] = c.y; v[3] = c.z; v[4] = c.w;
        v[0] = (x0 > 0)     ? __ldg(row + x0 - 1) : 0.0f;
        v[5] = (x0 + 4 < W) ? __ldg(row + x0 + 4) : 0.0f;
    } else {
        v[0] = v[1] = v[2] = v[3] = v[4] = v[5] = 0.0f;
    }
}

// Generic (border-capable) single output row of 4 pixels.
__device__ __forceinline__ void row_generic(const float* __restrict__ img,
                                            float* __restrict__ out,
                                            int y, int x0, int H, int W) {
    const bool has_up = (y > 0);
    const bool has_dn = (y < H - 1);

    float a[6], b[6], c[6];
    load6g(img + (size_t)(y - 1) * W, x0, W, has_up, a);
    load6g(img + (size_t)y * W,       x0, W, true,   b);
    load6g(img + (size_t)(y + 1) * W, x0, W, has_dn, c);

    const float rows_valid = 1.0f + (has_up ? 1.0f : 0.0f) + (has_dn ? 1.0f : 0.0f);

    float4 res;
    float* rp = reinterpret_cast<float*>(&res);
    #pragma unroll
    for (int i = 0; i < 4; i++) {
        const int x = x0 + i;
        const bool has_l = (x > 0);
        const bool has_r = (x < W - 1);

        const float sum9 = (a[i] + a[i + 1] + a[i + 2])
                         + (b[i] + b[i + 1] + b[i + 2])
                         + (c[i] + c[i + 1] + c[i + 2]);

        const float cols_valid = 1.0f + (has_l ? 1.0f : 0.0f) + (has_r ? 1.0f : 0.0f);
        const float count = rows_valid * cols_valid;
        const float coeff = 9.0f / count;
        const float mean  = (sum9 * (1.0f / 9.0f)) * coeff;

        const float v = b[i + 1];
        const bool mask = (v > THRE_TIMES * mean) || (v > THRE_POINT);

        const float nsum = b[i] + b[i + 2] + a[i + 1] + c[i + 1];
        const float cnt  = (has_up ? 1.0f : 0.0f) + (has_dn ? 1.0f : 0.0f)
                         + (has_l  ? 1.0f : 0.0f) + (has_r  ? 1.0f : 0.0f);
        const float repaired = floorf(nsum / cnt);

        rp[i] = mask ? repaired : v;
    }
    *reinterpret_cast<float4*>(out + (size_t)y * W + x0) = res;
}

__global__ void __launch_bounds__(256)
repair_kernel(const float* __restrict__ img, float* __restrict__ out,
              int H, int W) {
    const int lane = threadIdx.x;                       // blockDim.x == 32
    const int x0 = (blockIdx.x * 32 + lane) * 4;        // 4 px wide
    const int y0 = (blockIdx.y * blockDim.y + threadIdx.y) * 4;  // 4 px tall

    const bool valid = (x0 < W) && (y0 < H);
    // Interior: rows y0-1..y0+4 in-bounds, and x halos resolvable
    // (lane 0 edge load needs x0-1 >= 0; lane 31 edge load needs x0+4 <= W-1).
    const bool interior = valid && (x0 >= 4) && (x0 + 8 <= W)
                        && (y0 >= 1) && (y0 + 4 <= H - 1);

    if (__all_sync(FULL_MASK, interior)) {
        const float* base = img + (size_t)(y0 - 1) * W + x0;

        // 6 input rows, one float4 each (MLP batch), halos via shuffle.
        float4 c[6];
        #pragma unroll
        for (int r = 0; r < 6; r++)
            c[r] = *reinterpret_cast<const float4*>(base + (size_t)r * W);

        float L[6][6];
        #pragma unroll
        for (int r = 0; r < 6; r++) {
            float v0 = __shfl_up_sync(FULL_MASK, c[r].w, 1);
            float v5 = __shfl_down_sync(FULL_MASK, c[r].x, 1);
            if (lane == 0)  v0 = __ldg(base + (size_t)r * W - 1);
            if (lane == 31) v5 = __ldg(base + (size_t)r * W + 4);
            L[r][0] = v0;     L[r][1] = c[r].x; L[r][2] = c[r].y;
            L[r][3] = c[r].z; L[r][4] = c[r].w; L[r][5] = v5;
        }

        float* o = out + (size_t)y0 * W + x0;

        #pragma unroll
        for (int pr = 0; pr < 2; pr++) {
            const int k = 2 * pr;  // output rows y0+k, y0+k+1 use L[k..k+3]
            float t[6], WA[6], WB[6];
            #pragma unroll
            for (int j = 0; j < 6; j++) {
                t[j]  = L[k + 1][j] + L[k + 2][j];  // shared middle pair
                WA[j] = L[k][j] + t[j];
                WB[j] = t[j] + L[k + 3][j];
            }

            float4 ra, rb;
            float* pa = reinterpret_cast<float*>(&ra);
            float* pb = reinterpret_cast<float*>(&rb);

            #pragma unroll
            for (int i = 0; i < 4; i++) {
                {   // row y0+k
                    const float v    = L[k + 1][i + 1];
                    const float mean = (WA[i] + WA[i + 1] + WA[i + 2]) * (1.0f / 9.0f);
                    const bool  m    = (v > THRE_TIMES * mean) || (v > THRE_POINT);
                    const float ns   = L[k][i + 1] + L[k + 2][i + 1]
                                     + L[k + 1][i] + L[k + 1][i + 2];
                    pa[i] = m ? floorf(ns * 0.25f) : v;
                }
                {   // row y0+k+1
                    const float v    = L[k + 2][i + 1];
                    const float mean = (WB[i] + WB[i + 1] + WB[i + 2]) * (1.0f / 9.0f);
                    const bool  m    = (v > THRE_TIMES * mean) || (v > THRE_POINT);
                    const float ns   = L[k + 1][i + 1] + L[k + 3][i + 1]
                                     + L[k + 2][i] + L[k + 2][i + 2];
                    pb[i] = m ? floorf(ns * 0.25f) : v;
                }
            }

            *reinterpret_cast<float4*>(o + (size_t)k * W)       = ra;
            *reinterpret_cast<float4*>(o + (size_t)(k + 1) * W) = rb;
        }
    } else {
        if (!valid) return;
        #pragma unroll
        for (int r = 0; r < 4; r++)
            if (y0 + r < H) row_generic(img, out, y0 + r, x0, H, W);
    }
}

extern "C" void kernel_launch(void* const* d_in, const int* in_sizes, int n_in,
                              void* d_out, int out_size) {
    const float* img = (const float*)d_in[0];
    float* out = (float*)d_out;

    long long n = in_sizes[0];
    int side = (int)(sqrt((double)n) + 0.5);
    const int H = side, W = side;

    dim3 block(32, 8);                      // 256 threads; thread tile 4x4
    dim3 grid((W + 127) / 128,              // 32 lanes * 4 px
              (H + 31) / 32);               // 8 thread-rows * 4 px
    repair_kernel<<<grid, block>>>(img, out, H, W);
}

// round 12
// speedup vs baseline: 1.0145x; 1.0003x over previous
#include <cuda_runtime.h>
#include <math.h>

// DamagedPointRepair (8192x8192 fp32):
//   mean  = 3x3 zero-padded box mean * coeff (== in-bounds 3x3 average)
//   mask  = img > 5*mean || img > 1000
//   out   = mask ? floor(4-neighbor avg) : img
//
// R5: L1-wavefront reduction. Halos via warp shuffle (kills stride-16B scalar
// halo loads, which cost 4 L1 wavefronts each) + 4 output rows per thread
// (6 loaded rows per 4 output rows: redundancy 2.0x -> 1.5x).
// Border warps take the scalar generic path (warp-uniform branch).

#define THRE_TIMES 5.0f
#define THRE_POINT 1000.0f
#define FULL_MASK 0xffffffffu

__device__ __forceinline__ void load6g(const float* __restrict__ row, int x0, int W,
                                       bool valid, float v[6]) {
    if (valid) {
        const float4 c = *reinterpret_cast<const float4*>(row + x0);
        v[1] = c.x; v[2] = c.y; v[3] = c.z; v[4] = c.w;
        v[0] = (x0 > 0)     ? __ldg(row + x0 - 1) : 0.0f;
        v[5] = (x0 + 4 < W) ? __ldg(row + x0 + 4) : 0.0f;
    } else {
        v[0] = v[1] = v[2] = v[3] = v[4] = v[5] = 0.0f;
    }
}

// Generic (border-capable) single output row of 4 pixels.
__device__ __forceinline__ void row_generic(const float* __restrict__ img,
                                            float* __restrict__ out,
                                            int y, int x0, int H, int W) {
    const bool has_up = (y > 0);
    const bool has_dn = (y < H - 1);

    float a[6], b[6], c[6];
    load6g(img + (size_t)(y - 1) * W, x0, W, has_up, a);
    load6g(img + (size_t)y * W,       x0, W, true,   b);
    load6g(img + (size_t)(y + 1) * W, x0, W, has_dn, c);

    const float rows_valid = 1.0f + (has_up ? 1.0f : 0.0f) + (has_dn ? 1.0f : 0.0f);

    float4 res;
    float* rp = reinterpret_cast<float*>(&res);
    #pragma unroll
    for (int i = 0; i < 4; i++) {
        const int x = x0 + i;
        const bool has_l = (x > 0);
        const bool has_r = (x < W - 1);

        const float sum9 = (a[i] + a[i + 1] + a[i + 2])
                         + (b[i] + b[i + 1] + b[i + 2])
                         + (c[i] + c[i + 1] + c[i + 2]);

        const float cols_valid = 1.0f + (has_l ? 1.0f : 0.0f) + (has_r ? 1.0f : 0.0f);
        const float count = rows_valid * cols_valid;
        const float coeff = 9.0f / count;
        const float mean  = (sum9 * (1.0f / 9.0f)) * coeff;

        const float v = b[i + 1];
        const bool mask = (v > THRE_TIMES * mean) || (v > THRE_POINT);

        const float nsum = b[i] + b[i + 2] + a[i + 1] + c[i + 1];
        const float cnt  = (has_up ? 1.0f : 0.0f) + (has_dn ? 1.0f : 0.0f)
                         + (has_l  ? 1.0f : 0.0f) + (has_r  ? 1.0f : 0.0f);
        const float repaired = floorf(nsum / cnt);

        rp[i] = mask ? repaired : v;
    }
    *reinterpret_cast<float4*>(out + (size_t)y * W + x0) = res;
}

__global__ void __launch_bounds__(256)
repair_kernel(const float* __restrict__ img, float* __restrict__ out,
              int H, int W) {
    const int lane = threadIdx.x;                       // blockDim.x == 32
    const int x0 = (blockIdx.x * 32 + lane) * 4;        // 4 px wide
    const int y0 = (blockIdx.y * blockDim.y + threadIdx.y) * 4;  // 4 px tall

    const bool valid = (x0 < W) && (y0 < H);
    // Interior: rows y0-1..y0+4 in-bounds, and x halos resolvable
    // (lane 0 edge load needs x0-1 >= 0; lane 31 edge load needs x0+4 <= W-1).
    const bool interior = valid && (x0 >= 4) && (x0 + 8 <= W)
                        && (y0 >= 1) && (y0 + 4 <= H - 1);

    if (__all_sync(FULL_MASK, interior)) {
        const float* base = img + (size_t)(y0 - 1) * W + x0;

        // 6 input rows, one float4 each (MLP batch), halos via shuffle.
        float4 c[6];
        #pragma unroll
        for (int r = 0; r < 6; r++)
            c[r] = *reinterpret_cast<const float4*>(base + (size_t)r * W);

        float L[6][6];
        #pragma unroll
        for (int r = 0; r < 6; r++) {
            float v0 = __shfl_up_sync(FULL_MASK, c[r].w, 1);
            float v5 = __shfl_down_sync(FULL_MASK, c[r].x, 1);
            if (lane == 0)  v0 = __ldg(base + (size_t)r * W - 1);
            if (lane == 31) v5 = __ldg(base + (size_t)r * W + 4);
            L[r][0] = v0;     L[r][1] = c[r].x; L[r][2] = c[r].y;
            L[r][3] = c[r].z; L[r][4] = c[r].w; L[r][5] = v5;
        }

        float* o = out + (size_t)y0 * W + x0;

        #pragma unroll
        for (int pr = 0; pr < 2; pr++) {
            const int k = 2 * pr;  // output rows y0+k, y0+k+1 use L[k..k+3]
            float t[6], WA[6], WB[6];
            #pragma unroll
            for (int j = 0; j < 6; j++) {
                t[j]  = L[k + 1][j] + L[k + 2][j];  // shared middle pair
                WA[j] = L[k][j] + t[j];
                WB[j] = t[j] + L[k + 3][j];
            }

            float4 ra, rb;
            float* pa = reinterpret_cast<float*>(&ra);
            float* pb = reinterpret_cast<float*>(&rb);

            #pragma unroll
            for (int i = 0; i < 4; i++) {
                {   // row y0+k
                    const float v    = L[k + 1][i + 1];
                    const float mean = (WA[i] + WA[i + 1] + WA[i + 2]) * (1.0f / 9.0f);
                    const bool  m    = (v > THRE_TIMES * mean) || (v > THRE_POINT);
                    const float ns   = L[k][i + 1] + L[k + 2][i + 1]
                                     + L[k + 1][i] + L[k + 1][i + 2];
                    pa[i] = m ? floorf(ns * 0.25f) : v;
                }
                {   // row y0+k+1
                    const float v    = L[k + 2][i + 1];
                    const float mean = (WB[i] + WB[i + 1] + WB[i + 2]) * (1.0f / 9.0f);
                    const bool  m    = (v > THRE_TIMES * mean) || (v > THRE_POINT);
                    const float ns   = L[k + 1][i + 1] + L[k + 3][i + 1]
                                     + L[k + 2][i] + L[k + 2][i + 2];
                    pb[i] = m ? floorf(ns * 0.25f) : v;
                }
            }

            *reinterpret_cast<float4*>(o + (size_t)k * W)       = ra;
            *reinterpret_cast<float4*>(o + (size_t)(k + 1) * W) = rb;
        }
    } else {
        if (!valid) return;
        #pragma unroll
        for (int r = 0; r < 4; r++)
            if (y0 + r < H) row_generic(img, out, y0 + r, x0, H, W);
    }
}

extern "C" void kernel_launch(void* const* d_in, const int* in_sizes, int n_in,
                              void* d_out, int out_size) {
    const float* img = (const float*)d_in[0];
    float* out = (float*)d_out;

    long long n = in_sizes[0];
    int side = (int)(sqrt((double)n) + 0.5);
    const int H = side, W = side;

    dim3 block(32, 8);                      // 256 threads; thread tile 4x4
    dim3 grid((W + 127) / 128,              // 32 lanes * 4 px
              (H + 31) / 32);               // 8 thread-rows * 4 px
    repair_kernel<<<grid, block>>>(img, out, H, W);
}